// round 2
// baseline (speedup 1.0000x reference)
#include <cuda_runtime.h>

#define T 1024
#define BATCH 64

// Scratch (device globals — no allocations allowed)
__device__ float d_A1sm[3][1032];   // softmax(A1) + 8 zero pads
__device__ float d_tail[3][1024];   // (1-beta_a) + sig(-10)*suffix(A1sm, T-i)
__device__ float d_A2sm[3][1024];
__device__ float d_A4sm[3];
__device__ float d_S2[2][3][BATCH]; // per-sigma, per-branch, per-batch partial sums

__device__ __forceinline__ float clamp01(float v) { return fminf(fmaxf(v, 0.f), 1.f); }

// ---------------------------------------------------------------------------
// Block-wide reductions over 1024 threads
// ---------------------------------------------------------------------------
__device__ __forceinline__ float blockReduceMax1024(float v, float* sh32) {
    int w = threadIdx.x >> 5, l = threadIdx.x & 31;
    #pragma unroll
    for (int off = 16; off; off >>= 1) v = fmaxf(v, __shfl_xor_sync(0xffffffffu, v, off));
    if (l == 0) sh32[w] = v;
    __syncthreads();
    if (w == 0) {
        float x = sh32[l];
        #pragma unroll
        for (int off = 16; off; off >>= 1) x = fmaxf(x, __shfl_xor_sync(0xffffffffu, x, off));
        if (l == 0) sh32[0] = x;
    }
    __syncthreads();
    float r = sh32[0];
    __syncthreads();
    return r;
}

__device__ __forceinline__ float blockReduceSum1024(float v, float* sh32) {
    int w = threadIdx.x >> 5, l = threadIdx.x & 31;
    #pragma unroll
    for (int off = 16; off; off >>= 1) v += __shfl_xor_sync(0xffffffffu, v, off);
    if (l == 0) sh32[w] = v;
    __syncthreads();
    if (w == 0) {
        float x = sh32[l];
        #pragma unroll
        for (int off = 16; off; off >>= 1) x += __shfl_xor_sync(0xffffffffu, x, off);
        if (l == 0) sh32[0] = x;
    }
    __syncthreads();
    float r = sh32[0];
    __syncthreads();
    return r;
}

// ---------------------------------------------------------------------------
// Setup: 6 blocks x 1024 threads.
//   blocks 0-2: branch br = blk: softmax(A1) + suffix scan -> tail
//   blocks 3-5: branch br = blk-3: softmax(A2)   (+A4 softmax in block 3)
// ---------------------------------------------------------------------------
__global__ void __launch_bounds__(1024) setup_kernel(
    const float* __restrict__ A1a, const float* __restrict__ A1b, const float* __restrict__ A1c,
    const float* __restrict__ A2a, const float* __restrict__ A2b, const float* __restrict__ A2c,
    const float* __restrict__ A4,
    const float* __restrict__ ba1, const float* __restrict__ ba2, const float* __restrict__ ba3)
{
    __shared__ float sh[1024];
    __shared__ float sh32[32];
    __shared__ float swoff[32];
    int blk = blockIdx.x;
    int t = threadIdx.x;
    int w = t >> 5, l = t & 31;

    if (blk < 3) {
        int br = blk;
        const float* A1 = (br == 0) ? A1a : (br == 1) ? A1b : A1c;
        const float* bap = (br == 0) ? ba1 : (br == 1) ? ba2 : ba3;
        const float sig10 = 1.f / (1.f + expf(10.f));

        float v = A1[t];
        float m = blockReduceMax1024(v, sh32);
        float e = __expf(v - m);
        float ssum = blockReduceSum1024(e, sh32);
        float a1 = __fdividef(e, ssum);
        d_A1sm[br][t] = a1;
        if (t < 8) d_A1sm[br][1024 + t] = 0.f;

        // inclusive suffix scan: Ssuf[t] = sum_{j>=t} a1[j]
        float s = a1;
        #pragma unroll
        for (int off = 1; off < 32; off <<= 1) {
            float o = __shfl_down_sync(0xffffffffu, s, off);
            if (l + off < 32) s += o;
        }
        if (l == 0) sh32[w] = s;            // warp totals
        __syncthreads();
        if (w == 0) {
            float x = sh32[l];
            float inc = x;
            #pragma unroll
            for (int off = 1; off < 32; off <<= 1) {
                float o = __shfl_down_sync(0xffffffffu, inc, off);
                if (l + off < 32) inc += o;
            }
            float excl = __shfl_down_sync(0xffffffffu, inc, 1);
            if (l == 31) excl = 0.f;
            swoff[l] = excl;
        }
        __syncthreads();
        float Ssuf_t = s + swoff[w];
        sh[t] = Ssuf_t;
        __syncthreads();
        float ba = bap[0];
        float ssuf_for_i = (t == 0) ? 0.f : sh[1024 - t];
        d_tail[br][t] = (1.f - ba) + sig10 * ssuf_for_i;
    } else {
        int br = blk - 3;
        const float* A2 = (br == 0) ? A2a : (br == 1) ? A2b : A2c;
        float v2 = A2[t];
        float m2 = blockReduceMax1024(v2, sh32);
        float e2 = __expf(v2 - m2);
        float s2 = blockReduceSum1024(e2, sh32);
        d_A2sm[br][t] = __fdividef(e2, s2);

        if (br == 0 && t == 0) {
            float m = fmaxf(A4[0], fmaxf(A4[1], A4[2]));
            float e0 = __expf(A4[0] - m), e1 = __expf(A4[1] - m), ee2 = __expf(A4[2] - m);
            float s = e0 + e1 + ee2;
            d_A4sm[0] = e0 / s; d_A4sm[1] = e1 / s; d_A4sm[2] = ee2 / s;
        }
    }
}

// ---------------------------------------------------------------------------
// Main correlation kernel. 384 blocks = (branch, batch, sigma) x 256 threads.
// Block sigma owns interleaved quad-pairs qt = 2p+sigma (p = 0..63); each pair
// is a low quad i=[4qt..4qt+3] + mirrored high quad i=[1020-4qt..+3].
// 4 threads per pair, each taking a j-quarter of both quads. The block owns
// the COMPLETE wb1 for its i's, so the clip+A2-weight epilogue is local.
// ---------------------------------------------------------------------------
__device__ __forceinline__ void corr_loop(const float* __restrict__ sA,
                                          const float* __restrict__ g,
                                          int jb, int je, float* acc)
{
    if (jb >= je) return;
    float4 w = *(const float4*)(g + jb);
    for (int j = jb; j < je; j += 8) {
        float4 a0 = *(const float4*)(sA + j);
        float4 v  = *(const float4*)(g + j + 4);
        acc[0] = fmaf(a0.x, w.x, acc[0]); acc[1] = fmaf(a0.x, w.y, acc[1]);
        acc[2] = fmaf(a0.x, w.z, acc[2]); acc[3] = fmaf(a0.x, w.w, acc[3]);
        acc[0] = fmaf(a0.y, w.y, acc[0]); acc[1] = fmaf(a0.y, w.z, acc[1]);
        acc[2] = fmaf(a0.y, w.w, acc[2]); acc[3] = fmaf(a0.y, v.x, acc[3]);
        acc[0] = fmaf(a0.z, w.z, acc[0]); acc[1] = fmaf(a0.z, w.w, acc[1]);
        acc[2] = fmaf(a0.z, v.x, acc[2]); acc[3] = fmaf(a0.z, v.y, acc[3]);
        acc[0] = fmaf(a0.w, w.w, acc[0]); acc[1] = fmaf(a0.w, v.x, acc[1]);
        acc[2] = fmaf(a0.w, v.y, acc[2]); acc[3] = fmaf(a0.w, v.z, acc[3]);
        float4 a1 = *(const float4*)(sA + j + 4);
        float4 u  = *(const float4*)(g + j + 8);
        acc[0] = fmaf(a1.x, v.x, acc[0]); acc[1] = fmaf(a1.x, v.y, acc[1]);
        acc[2] = fmaf(a1.x, v.z, acc[2]); acc[3] = fmaf(a1.x, v.w, acc[3]);
        acc[0] = fmaf(a1.y, v.y, acc[0]); acc[1] = fmaf(a1.y, v.z, acc[1]);
        acc[2] = fmaf(a1.y, v.w, acc[2]); acc[3] = fmaf(a1.y, u.x, acc[3]);
        acc[0] = fmaf(a1.z, v.z, acc[0]); acc[1] = fmaf(a1.z, v.w, acc[1]);
        acc[2] = fmaf(a1.z, u.x, acc[2]); acc[3] = fmaf(a1.z, u.y, acc[3]);
        acc[0] = fmaf(a1.w, v.w, acc[0]); acc[1] = fmaf(a1.w, u.x, acc[1]);
        acc[2] = fmaf(a1.w, u.y, acc[2]); acc[3] = fmaf(a1.w, u.z, acc[3]);
        w = u;
    }
}

__global__ void __launch_bounds__(256) corr_kernel(
    const float* __restrict__ x1, const float* __restrict__ x2, const float* __restrict__ x3,
    const float* __restrict__ t1, const float* __restrict__ b1,
    const float* __restrict__ t2, const float* __restrict__ b2,
    const float* __restrict__ t3, const float* __restrict__ b3)
{
    __shared__ __align__(16) float sA[1032];
    __shared__ __align__(16) float sG[1040];
    __shared__ float sP[2048];

    int bid = blockIdx.x;              // 384 = br*128 + bb*2 + sigma
    int br = bid >> 7;
    int rem = bid & 127;
    int bb = rem >> 1;
    int sigma = rem & 1;

    const float* xs = (br == 0) ? x1 : (br == 1) ? x2 : x3;
    const float* tp = (br == 0) ? t1 : (br == 1) ? t2 : t3;
    const float* bp = (br == 0) ? b1 : (br == 1) ? b2 : b3;
    int t = threadIdx.x;

    float tv = tp[0];
    float bv = bp[0];

    for (int k = t; k < 1032; k += 256) sA[k] = d_A1sm[br][k];

    const float* xr = xs + bb * 1024;
    #pragma unroll
    for (int kk = 0; kk < 4; kk++) {
        int k = t + kk * 256;
        float xv = xr[k];
        float prod = __fmul_rn(xv, tv);      // no FMA contraction: exact r==b test
        float r = __fsub_rn(bv, prod);
        if (r == bv) r = -10.f;
        sG[k] = __fdividef(1.f, 1.f + __expf(-r));
    }
    if (t < 16) sG[1024 + t] = 0.f;          // zero pad: overshoot terms become exact zeros
    __syncthreads();

    int p = t >> 2;                 // pair index 0..63
    int c = t & 3;                  // j-quarter 0..3
    int qt = 2 * p + sigma;         // quad index 0..127
    int baseL = qt << 2;
    int baseH = 1020 - baseL;

    float acc[8];
    #pragma unroll
    for (int q = 0; q < 8; q++) acc[q] = 0.f;

    {   // low quad: i = baseL..baseL+3, j range [0, NL)
        int N = 1024 - baseL;
        int jb = (((N * c) >> 2) + 7) & ~7; if (c == 0) jb = 0;
        int je = (((N * (c + 1)) >> 2) + 7) & ~7;
        corr_loop(sA, sG + baseL, jb, je, acc);
    }
    {   // high quad: i = baseH..baseH+3, j range [0, NH)
        int N = baseL + 4;
        int jb = (((N * c) >> 2) + 7) & ~7; if (c == 0) jb = 0;
        int je = (((N * (c + 1)) >> 2) + 7) & ~7;
        corr_loop(sA, sG + baseH, jb, je, acc + 4);
    }

    #pragma unroll
    for (int q = 0; q < 8; q++) sP[q * 256 + t] = acc[q];
    __syncthreads();

    float local = 0.f;
    if (t < 64) {
        int p2 = t;
        int bL = ((2 * p2 + sigma) << 2);
        int bH = 1020 - bL;
        #pragma unroll
        for (int q = 0; q < 8; q++) {
            int i = (q < 4) ? (bL + q) : (bH + (q - 4));
            float wb1 = sP[q * 256 + 4 * p2 + 0] + sP[q * 256 + 4 * p2 + 1]
                      + sP[q * 256 + 4 * p2 + 2] + sP[q * 256 + 4 * p2 + 3]
                      + d_tail[br][i];
            float act = clamp01(wb1);
            local += d_A2sm[br][i] * (1.f - act);
        }
    }
    __syncthreads();
    sP[t] = local;
    __syncthreads();
    #pragma unroll
    for (int s = 128; s > 0; s >>= 1) {
        if (t < s) sP[t] += sP[t + s];
        __syncthreads();
    }
    if (t == 0) d_S2[sigma][br][bb] = sP[0];
}

// ---------------------------------------------------------------------------
// Final combine
// ---------------------------------------------------------------------------
__global__ void final_kernel(const float* __restrict__ bb1p, const float* __restrict__ bb2p,
                             const float* __restrict__ bb3p, const float* __restrict__ beta4p,
                             float* __restrict__ out)
{
    int b = threadIdx.x;
    if (b < BATCH) {
        float acc = beta4p[0];
        float S0 = d_S2[0][0][b] + d_S2[1][0][b];
        float S1 = d_S2[0][1][b] + d_S2[1][1][b];
        float S2 = d_S2[0][2][b] + d_S2[1][2][b];
        float r0 = clamp01(bb1p[0] - S0);
        float r1 = clamp01(bb2p[0] - S1);
        float r2 = clamp01(bb3p[0] - S2);
        acc -= d_A4sm[0] * (1.f - r0);
        acc -= d_A4sm[1] * (1.f - r1);
        acc -= d_A4sm[2] * (1.f - r2);
        out[b] = clamp01(acc);
    }
}

extern "C" void kernel_launch(void* const* d_in, const int* in_sizes, int n_in,
                              void* d_out, int out_size)
{
    const float* x1      = (const float*)d_in[0];
    const float* x2      = (const float*)d_in[1];
    const float* x3      = (const float*)d_in[2];
    const float* t1      = (const float*)d_in[3];
    const float* b1      = (const float*)d_in[4];
    const float* A1_1    = (const float*)d_in[5];
    const float* A2_1    = (const float*)d_in[6];
    const float* beta1_1 = (const float*)d_in[7];
    const float* beta1_2 = (const float*)d_in[8];
    const float* t2      = (const float*)d_in[9];
    const float* b2      = (const float*)d_in[10];
    const float* A1_2    = (const float*)d_in[11];
    const float* A2_2    = (const float*)d_in[12];
    const float* beta2_1 = (const float*)d_in[13];
    const float* beta2_2 = (const float*)d_in[14];
    const float* t3      = (const float*)d_in[15];
    const float* b3      = (const float*)d_in[16];
    const float* A1_3    = (const float*)d_in[17];
    const float* A2_3    = (const float*)d_in[18];
    const float* beta3_1 = (const float*)d_in[19];
    const float* beta3_2 = (const float*)d_in[20];
    const float* A4      = (const float*)d_in[21];
    const float* beta4   = (const float*)d_in[22];
    float* out = (float*)d_out;

    setup_kernel<<<6, 1024>>>(A1_1, A1_2, A1_3, A2_1, A2_2, A2_3, A4,
                              beta1_1, beta2_1, beta3_1);
    corr_kernel<<<384, 256>>>(x1, x2, x3, t1, b1, t2, b2, t3, b3);
    final_kernel<<<1, 64>>>(beta1_2, beta2_2, beta3_2, beta4, out);
}

// round 3
// speedup vs baseline: 1.5821x; 1.5821x over previous
#include <cuda_runtime.h>

#define T 1024
#define BATCH 64
#define NBLK 384   // 3 branches * 64 batch * 2 sigma

__device__ float d_S2[2][3][BATCH];   // per-sigma, per-branch, per-batch partials
__device__ int   d_ctr;               // zero-initialized; finisher resets to 0

__device__ __forceinline__ float clamp01(float v) { return fminf(fmaxf(v, 0.f), 1.f); }

// ---------------------------------------------------------------------------
// 256-thread block reductions (8 warps)
// ---------------------------------------------------------------------------
__device__ __forceinline__ float blockMax256(float v, float* sRed) {
    int w = threadIdx.x >> 5, l = threadIdx.x & 31;
    #pragma unroll
    for (int off = 16; off; off >>= 1) v = fmaxf(v, __shfl_xor_sync(0xffffffffu, v, off));
    if (l == 0) sRed[w] = v;
    __syncthreads();
    if (threadIdx.x == 0) {
        float m = sRed[0];
        #pragma unroll
        for (int k = 1; k < 8; k++) m = fmaxf(m, sRed[k]);
        sRed[0] = m;
    }
    __syncthreads();
    float r = sRed[0];
    __syncthreads();
    return r;
}

__device__ __forceinline__ float blockSum256(float v, float* sRed) {
    int w = threadIdx.x >> 5, l = threadIdx.x & 31;
    #pragma unroll
    for (int off = 16; off; off >>= 1) v += __shfl_xor_sync(0xffffffffu, v, off);
    if (l == 0) sRed[w] = v;
    __syncthreads();
    if (threadIdx.x == 0) {
        float s = sRed[0];
        #pragma unroll
        for (int k = 1; k < 8; k++) s += sRed[k];
        sRed[0] = s;
    }
    __syncthreads();
    float r = sRed[0];
    __syncthreads();
    return r;
}

// ---------------------------------------------------------------------------
// Inner triangular-correlation loop: 4 accumulators (i = base..base+3),
// j advances by 8 per iteration, 32 FMAs per iteration.
// ---------------------------------------------------------------------------
__device__ __forceinline__ void corr_loop(const float* __restrict__ sA,
                                          const float* __restrict__ g,
                                          int jb, int je, float* acc)
{
    if (jb >= je) return;
    float4 w = *(const float4*)(g + jb);
    for (int j = jb; j < je; j += 8) {
        float4 a0 = *(const float4*)(sA + j);
        float4 v  = *(const float4*)(g + j + 4);
        acc[0] = fmaf(a0.x, w.x, acc[0]); acc[1] = fmaf(a0.x, w.y, acc[1]);
        acc[2] = fmaf(a0.x, w.z, acc[2]); acc[3] = fmaf(a0.x, w.w, acc[3]);
        acc[0] = fmaf(a0.y, w.y, acc[0]); acc[1] = fmaf(a0.y, w.z, acc[1]);
        acc[2] = fmaf(a0.y, w.w, acc[2]); acc[3] = fmaf(a0.y, v.x, acc[3]);
        acc[0] = fmaf(a0.z, w.z, acc[0]); acc[1] = fmaf(a0.z, w.w, acc[1]);
        acc[2] = fmaf(a0.z, v.x, acc[2]); acc[3] = fmaf(a0.z, v.y, acc[3]);
        acc[0] = fmaf(a0.w, w.w, acc[0]); acc[1] = fmaf(a0.w, v.x, acc[1]);
        acc[2] = fmaf(a0.w, v.y, acc[2]); acc[3] = fmaf(a0.w, v.z, acc[3]);
        float4 a1 = *(const float4*)(sA + j + 4);
        float4 u  = *(const float4*)(g + j + 8);
        acc[0] = fmaf(a1.x, v.x, acc[0]); acc[1] = fmaf(a1.x, v.y, acc[1]);
        acc[2] = fmaf(a1.x, v.z, acc[2]); acc[3] = fmaf(a1.x, v.w, acc[3]);
        acc[0] = fmaf(a1.y, v.y, acc[0]); acc[1] = fmaf(a1.y, v.z, acc[1]);
        acc[2] = fmaf(a1.y, v.w, acc[2]); acc[3] = fmaf(a1.y, u.x, acc[3]);
        acc[0] = fmaf(a1.z, v.z, acc[0]); acc[1] = fmaf(a1.z, v.w, acc[1]);
        acc[2] = fmaf(a1.z, u.x, acc[2]); acc[3] = fmaf(a1.z, u.y, acc[3]);
        acc[0] = fmaf(a1.w, v.w, acc[0]); acc[1] = fmaf(a1.w, u.x, acc[1]);
        acc[2] = fmaf(a1.w, u.y, acc[2]); acc[3] = fmaf(a1.w, u.z, acc[3]);
        w = u;
    }
}

// ---------------------------------------------------------------------------
// Fused kernel: per-block preamble (softmaxes, suffix scan, sigmoid row),
// triangular correlation, block-local clip+weight epilogue, and an in-kernel
// "last block finishes" final combine.
//
// Block = (br, bb, sigma). sigma picks a contiguous half of the 128 mirrored
// quad-pairs p. Warp layout: c = warp>>1 is the j-quarter (constant per warp);
// lanes are consecutive pairs -> stride-4-float shared loads (conflict-free).
// ---------------------------------------------------------------------------
__global__ void __launch_bounds__(256) fused_kernel(
    const float* __restrict__ x1, const float* __restrict__ x2, const float* __restrict__ x3,
    const float* __restrict__ t1p, const float* __restrict__ b1p,
    const float* __restrict__ t2p, const float* __restrict__ b2p,
    const float* __restrict__ t3p, const float* __restrict__ b3p,
    const float* __restrict__ A1a, const float* __restrict__ A1b, const float* __restrict__ A1c,
    const float* __restrict__ A2a, const float* __restrict__ A2b, const float* __restrict__ A2c,
    const float* __restrict__ ba1, const float* __restrict__ ba2, const float* __restrict__ ba3,
    const float* __restrict__ bb1, const float* __restrict__ bb2, const float* __restrict__ bb3,
    const float* __restrict__ A4, const float* __restrict__ beta4p,
    float* __restrict__ out)
{
    __shared__ __align__(16) float sA[1032];     // softmax(A1) + 8 zero pad
    __shared__ __align__(16) float sG[1040];     // sigmoid row + 16 zero pad
    __shared__ __align__(16) float sSuf[1024];   // inclusive suffix sums of sA
    __shared__ float sP[2048];                   // j-quarter partials / reductions
    __shared__ float sRed[8];
    __shared__ float sWsum[8];
    __shared__ float sWexcl[8];
    __shared__ float sM2inv[2];                  // {A2 max, 1/A2 expsum}
    __shared__ int   sDone;

    const float SIG10 = 4.5397868702434395e-05f; // sigmoid(-10) in fp32

    int bid = blockIdx.x;                 // br*128 + bb*2 + sigma
    int br = bid >> 7;
    int rem = bid & 127;
    int bb = rem >> 1;
    int sigma = rem & 1;

    const float* xs  = (br == 0) ? x1  : (br == 1) ? x2  : x3;
    const float* tp  = (br == 0) ? t1p : (br == 1) ? t2p : t3p;
    const float* bp  = (br == 0) ? b1p : (br == 1) ? b2p : b3p;
    const float* A1  = (br == 0) ? A1a : (br == 1) ? A1b : A1c;
    const float* A2  = (br == 0) ? A2a : (br == 1) ? A2b : A2c;
    const float* bap = (br == 0) ? ba1 : (br == 1) ? ba2 : ba3;

    int t = threadIdx.x;
    int w = t >> 5, l = t & 31;

    // ---------------- preamble: sigmoid row g ----------------
    float tv = tp[0];
    float bv = bp[0];
    {
        const float* xr = xs + bb * 1024;
        float4 xv = *(const float4*)(xr + 4 * t);
        float rr[4] = {xv.x, xv.y, xv.z, xv.w};
        float4 gv;
        float* gp = (float*)&gv;
        #pragma unroll
        for (int q = 0; q < 4; q++) {
            float prod = __fmul_rn(rr[q], tv);    // no contraction: exact r==b test
            float r = __fsub_rn(bv, prod);
            if (r == bv) r = -10.f;
            gp[q] = __fdividef(1.f, 1.f + __expf(-r));
        }
        *(float4*)(sG + 4 * t) = gv;
        if (t < 16) sG[1024 + t] = 0.f;
    }

    // ---------------- preamble: softmax(A1) + suffix scan ----------------
    {
        float4 v4 = *(const float4*)(A1 + 4 * t);
        float m = fmaxf(fmaxf(v4.x, v4.y), fmaxf(v4.z, v4.w));
        float M = blockMax256(m, sRed);
        float e0 = __expf(v4.x - M), e1 = __expf(v4.y - M);
        float e2 = __expf(v4.z - M), e3 = __expf(v4.w - M);
        float st = ((e0 + e1) + (e2 + e3));
        float SUM = blockSum256(st, sRed);
        float inv = __fdividef(1.f, SUM);
        float a0 = e0 * inv, a1 = e1 * inv, a2 = e2 * inv, a3 = e3 * inv;
        float4 av = {a0, a1, a2, a3};
        *(float4*)(sA + 4 * t) = av;
        if (t < 8) sA[1024 + t] = 0.f;

        // inclusive suffix scan over thread chunk sums
        float sn = ((a0 + a1) + (a2 + a3));
        float s = sn;
        #pragma unroll
        for (int off = 1; off < 32; off <<= 1) {
            float o = __shfl_down_sync(0xffffffffu, s, off);
            if (l + off < 32) s += o;
        }
        if (l == 0) sWsum[w] = s;      // warp total = inclusive suffix at lane 0
        __syncthreads();
        if (t < 8) {
            float tot = 0.f;
            for (int k = t + 1; k < 8; k++) tot += sWsum[k];
            sWexcl[t] = tot;           // sum of warps after mine
        }
        __syncthreads();
        float after = (s - sn) + sWexcl[w];   // strictly-after my chunk
        float v3s = after + a3;
        float v2s = v3s + a2;
        float v1s = v2s + a1;
        float v0s = v1s + a0;
        sSuf[4 * t + 3] = v3s;
        sSuf[4 * t + 2] = v2s;
        sSuf[4 * t + 1] = v1s;
        sSuf[4 * t + 0] = v0s;
    }

    // ---------------- preamble: softmax(A2) max & sum ----------------
    {
        float4 v4 = *(const float4*)(A2 + 4 * t);
        float m = fmaxf(fmaxf(v4.x, v4.y), fmaxf(v4.z, v4.w));
        float M2 = blockMax256(m, sRed);
        float st = __expf(v4.x - M2) + __expf(v4.y - M2)
                 + __expf(v4.z - M2) + __expf(v4.w - M2);
        float S2 = blockSum256(st, sRed);
        if (t == 0) { sM2inv[0] = M2; sM2inv[1] = __fdividef(1.f, S2); }
    }
    __syncthreads();

    // ---------------- main triangular correlation ----------------
    int c = w >> 1;                          // j-quarter, constant per warp
    int p = sigma * 64 + ((w & 1) << 5) + l; // pair index, lanes consecutive
    int baseL = 4 * p;
    int baseH = 1020 - baseL;

    float acc[8];
    #pragma unroll
    for (int q = 0; q < 8; q++) acc[q] = 0.f;

    {   // low quad: i = baseL..baseL+3
        int N = 1024 - baseL;
        int jb = (c == 0) ? 0 : ((((N * c) >> 2) + 7) & ~7);
        int je = ((((N * (c + 1)) >> 2) + 7) & ~7);
        corr_loop(sA, sG + baseL, jb, je, acc);
    }
    {   // high quad: i = baseH..baseH+3
        int N = baseL + 4;
        int jb = (c == 0) ? 0 : ((((N * c) >> 2) + 7) & ~7);
        int je = ((((N * (c + 1)) >> 2) + 7) & ~7);
        corr_loop(sA, sG + baseH, jb, je, acc + 4);
    }

    #pragma unroll
    for (int q = 0; q < 8; q++) sP[q * 256 + t] = acc[q];
    __syncthreads();

    // ---------------- epilogue: merge j-quarters, clip, A2-weight ----------------
    float local = 0.f;
    if (t < 64) {
        int pg = sigma * 64 + t;
        int bL = 4 * pg;
        int bH = 1020 - bL;
        float ba = bap[0];
        float M2 = sM2inv[0], invS2 = sM2inv[1];
        int lo = ((t >> 5) << 5) + (t & 31);   // = t; lane slot within half
        #pragma unroll
        for (int q = 0; q < 8; q++) {
            int i = (q < 4) ? (bL + q) : (bH + (q - 4));
            float s4 = 0.f;
            #pragma unroll
            for (int cc = 0; cc < 4; cc++) {
                int tid = ((2 * cc + (t >> 5)) << 5) + (t & 31);
                s4 += sP[q * 256 + tid];
            }
            float ssuf = (i == 0) ? 0.f : sSuf[1024 - i];
            float wb1 = s4 + (1.f - ba) + SIG10 * ssuf;
            float act = clamp01(wb1);
            float a2sm = __expf(A2[i] - M2) * invS2;
            local += a2sm * (1.f - act);
        }
        (void)lo;
    }
    __syncthreads();
    sP[t] = local;
    __syncthreads();
    #pragma unroll
    for (int s = 128; s > 0; s >>= 1) {
        if (t < s) sP[t] += sP[t + s];
        __syncthreads();
    }
    if (t == 0) d_S2[sigma][br][bb] = sP[0];

    // ---------------- last-block final combine ----------------
    __threadfence();
    if (t == 0) {
        int v = atomicAdd(&d_ctr, 1);
        sDone = (v == NBLK - 1) ? 1 : 0;
    }
    __syncthreads();
    if (sDone) {
        if (t < BATCH) {
            float e0 = __expf(A4[0]), e1 = __expf(A4[1]), e2 = __expf(A4[2]);
            float sinv = __fdividef(1.f, e0 + e1 + e2);
            float a40 = e0 * sinv, a41 = e1 * sinv, a42 = e2 * sinv;

            volatile float* vs = (volatile float*)d_S2;
            // layout: d_S2[sigma][br][b] -> vs[sigma*192 + br*64 + b]
            float S0 = vs[0 * 192 + 0 * 64 + t] + vs[1 * 192 + 0 * 64 + t];
            float S1 = vs[0 * 192 + 1 * 64 + t] + vs[1 * 192 + 1 * 64 + t];
            float S2 = vs[0 * 192 + 2 * 64 + t] + vs[1 * 192 + 2 * 64 + t];
            float r0 = clamp01(bb1[0] - S0);
            float r1 = clamp01(bb2[0] - S1);
            float r2 = clamp01(bb3[0] - S2);
            float acc4 = beta4p[0];
            acc4 -= a40 * (1.f - r0);
            acc4 -= a41 * (1.f - r1);
            acc4 -= a42 * (1.f - r2);
            out[t] = clamp01(acc4);
        }
        if (t == 0) d_ctr = 0;   // reset for next graph replay
    }
}

extern "C" void kernel_launch(void* const* d_in, const int* in_sizes, int n_in,
                              void* d_out, int out_size)
{
    const float* x1      = (const float*)d_in[0];
    const float* x2      = (const float*)d_in[1];
    const float* x3      = (const float*)d_in[2];
    const float* t1      = (const float*)d_in[3];
    const float* b1      = (const float*)d_in[4];
    const float* A1_1    = (const float*)d_in[5];
    const float* A2_1    = (const float*)d_in[6];
    const float* beta1_1 = (const float*)d_in[7];
    const float* beta1_2 = (const float*)d_in[8];
    const float* t2      = (const float*)d_in[9];
    const float* b2      = (const float*)d_in[10];
    const float* A1_2    = (const float*)d_in[11];
    const float* A2_2    = (const float*)d_in[12];
    const float* beta2_1 = (const float*)d_in[13];
    const float* beta2_2 = (const float*)d_in[14];
    const float* t3      = (const float*)d_in[15];
    const float* b3      = (const float*)d_in[16];
    const float* A1_3    = (const float*)d_in[17];
    const float* A2_3    = (const float*)d_in[18];
    const float* beta3_1 = (const float*)d_in[19];
    const float* beta3_2 = (const float*)d_in[20];
    const float* A4      = (const float*)d_in[21];
    const float* beta4   = (const float*)d_in[22];
    float* out = (float*)d_out;

    fused_kernel<<<NBLK, 256>>>(x1, x2, x3,
                                t1, b1, t2, b2, t3, b3,
                                A1_1, A1_2, A1_3,
                                A2_1, A2_2, A2_3,
                                beta1_1, beta2_1, beta3_1,
                                beta1_2, beta2_2, beta3_2,
                                A4, beta4, out);
}

// round 4
// speedup vs baseline: 1.5850x; 1.0019x over previous
#include <cuda_runtime.h>

#define T 1024
#define BATCH 64
#define NBLK 384   // 3 branches * 64 batch * 2 sigma

__device__ float d_S2[2][3][BATCH];   // per-sigma, per-branch, per-batch partials
__device__ int   d_ctr;               // zero-initialized; finisher resets to 0

__device__ __forceinline__ float clamp01(float v) { return fminf(fmaxf(v, 0.f), 1.f); }

// ---------------------------------------------------------------------------
// 256-thread block reductions (8 warps)
// ---------------------------------------------------------------------------
__device__ __forceinline__ float blockMax256(float v, float* sRed) {
    int w = threadIdx.x >> 5, l = threadIdx.x & 31;
    #pragma unroll
    for (int off = 16; off; off >>= 1) v = fmaxf(v, __shfl_xor_sync(0xffffffffu, v, off));
    if (l == 0) sRed[w] = v;
    __syncthreads();
    if (threadIdx.x == 0) {
        float m = sRed[0];
        #pragma unroll
        for (int k = 1; k < 8; k++) m = fmaxf(m, sRed[k]);
        sRed[0] = m;
    }
    __syncthreads();
    float r = sRed[0];
    __syncthreads();
    return r;
}

__device__ __forceinline__ float blockSum256(float v, float* sRed) {
    int w = threadIdx.x >> 5, l = threadIdx.x & 31;
    #pragma unroll
    for (int off = 16; off; off >>= 1) v += __shfl_xor_sync(0xffffffffu, v, off);
    if (l == 0) sRed[w] = v;
    __syncthreads();
    if (threadIdx.x == 0) {
        float s = sRed[0];
        #pragma unroll
        for (int k = 1; k < 8; k++) s += sRed[k];
        sRed[0] = s;
    }
    __syncthreads();
    float r = sRed[0];
    __syncthreads();
    return r;
}

// ---------------------------------------------------------------------------
// One 16-wide i-tile: acc[ii] += sum over this lane's j-slice of
//   sA[j] * sGb[ii + j],  j = 4*lane + 128*k + jj, jj = 0..3, k = 0..K-1.
// All lanes share K and base -> no divergence; all LDS are 16B-lane-stride
// (conflict-free). 64 FMA + 6 LDS.128 per iteration.
// ---------------------------------------------------------------------------
__device__ __forceinline__ void tile16(const float* __restrict__ sA,
                                       const float* __restrict__ sGb,
                                       int K, int lane, float* __restrict__ acc)
{
    const float* ap = sA + 4 * lane;
    const float* gp = sGb + 4 * lane;
    for (int k = 0; k < K; k++) {
        float av[4];
        *(float4*)av = *(const float4*)ap;
        float gv[20];
        *(float4*)(gv + 0)  = *(const float4*)(gp + 0);
        *(float4*)(gv + 4)  = *(const float4*)(gp + 4);
        *(float4*)(gv + 8)  = *(const float4*)(gp + 8);
        *(float4*)(gv + 12) = *(const float4*)(gp + 12);
        *(float4*)(gv + 16) = *(const float4*)(gp + 16);
        #pragma unroll
        for (int ii = 0; ii < 16; ii++) {
            #pragma unroll
            for (int jj = 0; jj < 4; jj++)
                acc[ii] = fmaf(av[jj], gv[ii + jj], acc[ii]);
        }
        ap += 128;
        gp += 128;
    }
}

// ---------------------------------------------------------------------------
// Fused kernel. Block = (br, bb, sigma). Each warp owns 2 mirrored tile-pairs.
// ---------------------------------------------------------------------------
__global__ void __launch_bounds__(256) fused_kernel(
    const float* __restrict__ x1, const float* __restrict__ x2, const float* __restrict__ x3,
    const float* __restrict__ t1p, const float* __restrict__ b1p,
    const float* __restrict__ t2p, const float* __restrict__ b2p,
    const float* __restrict__ t3p, const float* __restrict__ b3p,
    const float* __restrict__ A1a, const float* __restrict__ A1b, const float* __restrict__ A1c,
    const float* __restrict__ A2a, const float* __restrict__ A2b, const float* __restrict__ A2c,
    const float* __restrict__ ba1, const float* __restrict__ ba2, const float* __restrict__ ba3,
    const float* __restrict__ bb1, const float* __restrict__ bb2, const float* __restrict__ bb3,
    const float* __restrict__ A4, const float* __restrict__ beta4p,
    float* __restrict__ out)
{
    __shared__ __align__(16) float sA[1152];     // softmax(A1), zeros beyond 1023
    __shared__ __align__(16) float sG[1184];     // sigmoid row, zeros beyond 1023
    __shared__ __align__(16) float sSuf[1024];   // inclusive suffix sums of sA
    __shared__ float sStage[8][16 * 33];         // per-warp reduce staging
    __shared__ float sW[512];                    // per-tile wb1 partial sums
    __shared__ float sRed[8];
    __shared__ float sWsum[8];
    __shared__ float sWexcl[8];
    __shared__ float sM2inv[2];                  // {A2 max, 1/A2 expsum}
    __shared__ float sBlk[256];
    __shared__ int   sDone;

    const float SIG10 = 4.5397868702434395e-05f; // sigmoid(-10) in fp32

    int bid = blockIdx.x;                 // br*128 + bb*2 + sigma
    int br = bid >> 7;
    int rem = bid & 127;
    int bb = rem >> 1;
    int sigma = rem & 1;

    const float* xs  = (br == 0) ? x1  : (br == 1) ? x2  : x3;
    const float* tp  = (br == 0) ? t1p : (br == 1) ? t2p : t3p;
    const float* bp  = (br == 0) ? b1p : (br == 1) ? b2p : b3p;
    const float* A1  = (br == 0) ? A1a : (br == 1) ? A1b : A1c;
    const float* A2  = (br == 0) ? A2a : (br == 1) ? A2b : A2c;
    const float* bap = (br == 0) ? ba1 : (br == 1) ? ba2 : ba3;

    int t = threadIdx.x;
    int w = t >> 5, l = t & 31;

    // ---------------- preamble: sigmoid row g ----------------
    float tv = tp[0];
    float bv = bp[0];
    {
        const float* xr = xs + bb * 1024;
        float4 xv = *(const float4*)(xr + 4 * t);
        float rr[4] = {xv.x, xv.y, xv.z, xv.w};
        float4 gvv;
        float* gp2 = (float*)&gvv;
        #pragma unroll
        for (int q = 0; q < 4; q++) {
            float prod = __fmul_rn(rr[q], tv);    // no contraction: exact r==b test
            float r = __fsub_rn(bv, prod);
            if (r == bv) r = -10.f;
            gp2[q] = __fdividef(1.f, 1.f + __expf(-r));
        }
        *(float4*)(sG + 4 * t) = gvv;
        if (t < 160) sG[1024 + t] = 0.f;
    }

    // ---------------- preamble: softmax(A1) + suffix scan ----------------
    {
        float4 v4 = *(const float4*)(A1 + 4 * t);
        float m = fmaxf(fmaxf(v4.x, v4.y), fmaxf(v4.z, v4.w));
        float M = blockMax256(m, sRed);
        float e0 = __expf(v4.x - M), e1 = __expf(v4.y - M);
        float e2 = __expf(v4.z - M), e3 = __expf(v4.w - M);
        float st = ((e0 + e1) + (e2 + e3));
        float SUM = blockSum256(st, sRed);
        float inv = __fdividef(1.f, SUM);
        float a0 = e0 * inv, a1 = e1 * inv, a2 = e2 * inv, a3 = e3 * inv;
        float4 av = {a0, a1, a2, a3};
        *(float4*)(sA + 4 * t) = av;
        if (t < 128) sA[1024 + t] = 0.f;

        // inclusive suffix scan over 4-element thread chunks
        float sn = ((a0 + a1) + (a2 + a3));
        float s = sn;
        #pragma unroll
        for (int off = 1; off < 32; off <<= 1) {
            float o = __shfl_down_sync(0xffffffffu, s, off);
            if (l + off < 32) s += o;
        }
        if (l == 0) sWsum[w] = s;
        __syncthreads();
        if (t < 8) {
            float tot = 0.f;
            for (int k = t + 1; k < 8; k++) tot += sWsum[k];
            sWexcl[t] = tot;
        }
        __syncthreads();
        float after = (s - sn) + sWexcl[w];   // strictly-after my chunk
        float v3s = after + a3;
        float v2s = v3s + a2;
        float v1s = v2s + a1;
        float v0s = v1s + a0;
        sSuf[4 * t + 3] = v3s;
        sSuf[4 * t + 2] = v2s;
        sSuf[4 * t + 1] = v1s;
        sSuf[4 * t + 0] = v0s;
    }

    // ---------------- preamble: softmax(A2) max & sum ----------------
    {
        float4 v4 = *(const float4*)(A2 + 4 * t);
        float m = fmaxf(fmaxf(v4.x, v4.y), fmaxf(v4.z, v4.w));
        float M2 = blockMax256(m, sRed);
        float st = __expf(v4.x - M2) + __expf(v4.y - M2)
                 + __expf(v4.z - M2) + __expf(v4.w - M2);
        float S2 = blockSum256(st, sRed);
        if (t == 0) { sM2inv[0] = M2; sM2inv[1] = __fdividef(1.f, S2); }
    }
    __syncthreads();

    // ---------------- main triangular correlation ----------------
    // Warp w handles local pairs lp = 2w, 2w+1. Global pair q = sigma*16+lp.
    // Low tile i = 16q..16q+15, high tile i = 1008-16q..+15.
    float* st = &sStage[w][0];
    #pragma unroll
    for (int pp = 0; pp < 2; pp++) {
        int lp = 2 * w + pp;
        int q = sigma * 16 + lp;
        int bL = 16 * q;
        int bH = 1008 - 16 * q;

        #pragma unroll
        for (int hv = 0; hv < 2; hv++) {
            int base = hv ? bH : bL;
            int N = 1024 - base;
            int K = (N + 127) >> 7;

            float acc[16];
            #pragma unroll
            for (int ii = 0; ii < 16; ii++) acc[ii] = 0.f;

            tile16(sA, sG + base, K, l, acc);

            // warp-local reduction of 16 accs over 32 lanes
            #pragma unroll
            for (int ii = 0; ii < 16; ii++) st[ii * 33 + l] = acc[ii];
            __syncwarp();
            {
                int r = l >> 1, h = l & 1;   // lane -> (row r, half h)
                float s = 0.f;
                const float* row = st + r * 33 + 16 * h;
                #pragma unroll
                for (int k2 = 0; k2 < 16; k2++) s += row[k2];
                s += __shfl_xor_sync(0xffffffffu, s, 1);
                if (h == 0) sW[(lp * 2 + hv) * 16 + r] = s;
            }
            __syncwarp();
        }
    }
    __syncthreads();

    // ---------------- epilogue: tail, clip, A2-weight ----------------
    float local = 0.f;
    {
        float ba = bap[0];
        float M2 = sM2inv[0], invS2 = sM2inv[1];
        #pragma unroll
        for (int h = 0; h < 2; h++) {
            int v = 2 * t + h;            // 0..511
            int slot = v >> 4;            // 0..31
            int ii = v & 15;
            int lp = slot >> 1;
            int hi = slot & 1;
            int q = sigma * 16 + lp;
            int i = hi ? (1008 - 16 * q + ii) : (16 * q + ii);
            float ssuf = (i == 0) ? 0.f : sSuf[1024 - i];
            float wb1 = sW[v] + (1.f - ba) + SIG10 * ssuf;
            float act = clamp01(wb1);
            float a2sm = __expf(A2[i] - M2) * invS2;
            local += a2sm * (1.f - act);
        }
    }
    sBlk[t] = local;
    __syncthreads();
    #pragma unroll
    for (int s = 128; s > 0; s >>= 1) {
        if (t < s) sBlk[t] += sBlk[t + s];
        __syncthreads();
    }
    if (t == 0) d_S2[sigma][br][bb] = sBlk[0];

    // ---------------- last-block final combine ----------------
    __threadfence();
    if (t == 0) {
        int v = atomicAdd(&d_ctr, 1);
        sDone = (v == NBLK - 1) ? 1 : 0;
    }
    __syncthreads();
    if (sDone) {
        if (t < BATCH) {
            float e0 = __expf(A4[0]), e1 = __expf(A4[1]), e2 = __expf(A4[2]);
            float sinv = __fdividef(1.f, e0 + e1 + e2);
            float a40 = e0 * sinv, a41 = e1 * sinv, a42 = e2 * sinv;

            volatile float* vs = (volatile float*)d_S2;
            // d_S2[sigma][br][b] -> vs[sigma*192 + br*64 + b]
            float S0 = vs[0 * 192 + 0 * 64 + t] + vs[1 * 192 + 0 * 64 + t];
            float S1 = vs[0 * 192 + 1 * 64 + t] + vs[1 * 192 + 1 * 64 + t];
            float S2 = vs[0 * 192 + 2 * 64 + t] + vs[1 * 192 + 2 * 64 + t];
            float r0 = clamp01(bb1[0] - S0);
            float r1 = clamp01(bb2[0] - S1);
            float r2 = clamp01(bb3[0] - S2);
            float acc4 = beta4p[0];
            acc4 -= a40 * (1.f - r0);
            acc4 -= a41 * (1.f - r1);
            acc4 -= a42 * (1.f - r2);
            out[t] = clamp01(acc4);
        }
        if (t == 0) d_ctr = 0;   // reset for next graph replay
    }
}

extern "C" void kernel_launch(void* const* d_in, const int* in_sizes, int n_in,
                              void* d_out, int out_size)
{
    const float* x1      = (const float*)d_in[0];
    const float* x2      = (const float*)d_in[1];
    const float* x3      = (const float*)d_in[2];
    const float* t1      = (const float*)d_in[3];
    const float* b1      = (const float*)d_in[4];
    const float* A1_1    = (const float*)d_in[5];
    const float* A2_1    = (const float*)d_in[6];
    const float* beta1_1 = (const float*)d_in[7];
    const float* beta1_2 = (const float*)d_in[8];
    const float* t2      = (const float*)d_in[9];
    const float* b2      = (const float*)d_in[10];
    const float* A1_2    = (const float*)d_in[11];
    const float* A2_2    = (const float*)d_in[12];
    const float* beta2_1 = (const float*)d_in[13];
    const float* beta2_2 = (const float*)d_in[14];
    const float* t3      = (const float*)d_in[15];
    const float* b3      = (const float*)d_in[16];
    const float* A1_3    = (const float*)d_in[17];
    const float* A2_3    = (const float*)d_in[18];
    const float* beta3_1 = (const float*)d_in[19];
    const float* beta3_2 = (const float*)d_in[20];
    const float* A4      = (const float*)d_in[21];
    const float* beta4   = (const float*)d_in[22];
    float* out = (float*)d_out;

    fused_kernel<<<NBLK, 256>>>(x1, x2, x3,
                                t1, b1, t2, b2, t3, b3,
                                A1_1, A1_2, A1_3,
                                A2_1, A2_2, A2_3,
                                beta1_1, beta2_1, beta3_1,
                                beta1_2, beta2_2, beta3_2,
                                A4, beta4, out);
}